// round 1
// baseline (speedup 1.0000x reference)
#include <cuda_runtime.h>

// Problem constants (fixed by the dataset)
#define NN 100000
#define EE 1600000

// Scratch (allocation-free rule: __device__ globals)
__device__ float g_dinv[NN];
__device__ float g_u[(size_t)NN * 64];
__device__ float g_acc[(size_t)NN * 64];
__device__ float g_h[(size_t)NN * 64];

// ---------------------------------------------------------------------------
// Degree / normalization
// ---------------------------------------------------------------------------
__global__ void k_deg_init(int n) {
    int i = blockIdx.x * blockDim.x + threadIdx.x;
    if (i < n) g_dinv[i] = 1.0f;  // self-loop contributes 1 to degree
}

__global__ void k_deg_count(const int* __restrict__ dst, int e) {
    int i = blockIdx.x * blockDim.x + threadIdx.x;
    if (i < e) atomicAdd(&g_dinv[dst[i]], 1.0f);
}

__global__ void k_deg_rsqrt(int n) {
    int i = blockIdx.x * blockDim.x + threadIdx.x;
    if (i < n) g_dinv[i] = rsqrtf(g_dinv[i]);  // deg >= 1 always
}

__global__ void k_zero_acc(int n4) {
    int i = blockIdx.x * blockDim.x + threadIdx.x;
    if (i < n4) ((float4*)g_acc)[i] = make_float4(0.f, 0.f, 0.f, 0.f);
}

// ---------------------------------------------------------------------------
// Dense transform:  u[row] = dinv[row] * (hin[row] @ W)
// One thread per node row, W staged in shared (broadcast LDS.128 reads).
// ---------------------------------------------------------------------------
template <int IN, int OUT>
__global__ void k_transform(const float* __restrict__ hin,
                            const float* __restrict__ W, int n) {
    __shared__ float sW[IN * OUT];
    for (int i = threadIdx.x; i < IN * OUT / 4; i += blockDim.x)
        ((float4*)sW)[i] = ((const float4*)W)[i];
    __syncthreads();

    int row = blockIdx.x * blockDim.x + threadIdx.x;
    if (row >= n) return;

    float acc[OUT];
#pragma unroll
    for (int c = 0; c < OUT; c++) acc[c] = 0.f;

    const float4* hr = (const float4*)(hin + (size_t)row * IN);
#pragma unroll 1
    for (int k4 = 0; k4 < IN / 4; k4++) {
        float4 xv = hr[k4];
        const float4* w0 = (const float4*)(sW + (k4 * 4 + 0) * OUT);
        const float4* w1 = (const float4*)(sW + (k4 * 4 + 1) * OUT);
        const float4* w2 = (const float4*)(sW + (k4 * 4 + 2) * OUT);
        const float4* w3 = (const float4*)(sW + (k4 * 4 + 3) * OUT);
#pragma unroll
        for (int c4 = 0; c4 < OUT / 4; c4++) {
            float4 q0 = w0[c4], q1 = w1[c4], q2 = w2[c4], q3 = w3[c4];
            acc[4 * c4 + 0] += xv.x * q0.x + xv.y * q1.x + xv.z * q2.x + xv.w * q3.x;
            acc[4 * c4 + 1] += xv.x * q0.y + xv.y * q1.y + xv.z * q2.y + xv.w * q3.y;
            acc[4 * c4 + 2] += xv.x * q0.z + xv.y * q1.z + xv.z * q2.z + xv.w * q3.z;
            acc[4 * c4 + 3] += xv.x * q0.w + xv.y * q1.w + xv.z * q2.w + xv.w * q3.w;
        }
    }

    float dv = g_dinv[row];
    float4* ur = (float4*)(g_u + (size_t)row * OUT);
#pragma unroll
    for (int c4 = 0; c4 < OUT / 4; c4++)
        ur[c4] = make_float4(dv * acc[4 * c4 + 0], dv * acc[4 * c4 + 1],
                             dv * acc[4 * c4 + 2], dv * acc[4 * c4 + 3]);
}

// ---------------------------------------------------------------------------
// Scatter: acc[dst] += u[src]   (OUT/4 lanes cooperate on one edge)
// Uses sm_90+ vector reduction (no return) -> 16B per atomic op.
// ---------------------------------------------------------------------------
template <int OUT>
__global__ void k_scatter(const int* __restrict__ src,
                          const int* __restrict__ dst, int e) {
    constexpr int LPE = OUT / 4;  // lanes per edge
    int t = blockIdx.x * blockDim.x + threadIdx.x;
    int edge = t / LPE;
    int lane = t - edge * LPE;
    if (edge >= e) return;
    int s = src[edge];
    int d = dst[edge];
    float4 v = ((const float4*)g_u)[(size_t)s * LPE + lane];
    float4* a = ((float4*)g_acc) + (size_t)d * LPE + lane;
    asm volatile("red.global.add.v4.f32 [%0], {%1,%2,%3,%4};"
                 :: "l"(a), "f"(v.x), "f"(v.y), "f"(v.z), "f"(v.w)
                 : "memory");
}

// ---------------------------------------------------------------------------
// Finish: h[row] = relu(dinv[row]*(acc[row] + u[row]) + b)
//   (the +u term is the self-loop: dinv_i * (dinv_i * t_i))
// Also re-zeroes acc for the next layer's scatter.
// ---------------------------------------------------------------------------
template <int OUT>
__global__ void k_finish(const float* __restrict__ b, int n) {
    constexpr int C4 = OUT / 4;
    int t = blockIdx.x * blockDim.x + threadIdx.x;
    int row = t / C4;
    int c4 = t - row * C4;
    if (row >= n) return;
    float dv = g_dinv[row];
    size_t off = (size_t)row * C4 + c4;
    float4 a = ((float4*)g_acc)[off];
    float4 u = ((const float4*)g_u)[off];
    float4 bb = ((const float4*)b)[c4];
    float4 r;
    r.x = fmaxf(dv * (a.x + u.x) + bb.x, 0.f);
    r.y = fmaxf(dv * (a.y + u.y) + bb.y, 0.f);
    r.z = fmaxf(dv * (a.z + u.z) + bb.z, 0.f);
    r.w = fmaxf(dv * (a.w + u.w) + bb.w, 0.f);
    ((float4*)g_h)[off] = r;
    ((float4*)g_acc)[off] = make_float4(0.f, 0.f, 0.f, 0.f);
}

// ---------------------------------------------------------------------------
// Head: out[row] = h4[row](32) @ Wh(32x3) + bh
// ---------------------------------------------------------------------------
__global__ void k_head(const float* __restrict__ Wh, const float* __restrict__ bh,
                       float* __restrict__ out, int n) {
    __shared__ float sW[96];
    __shared__ float sb[3];
    if (threadIdx.x < 96) sW[threadIdx.x] = Wh[threadIdx.x];
    if (threadIdx.x < 3) sb[threadIdx.x] = bh[threadIdx.x];
    __syncthreads();
    int row = blockIdx.x * blockDim.x + threadIdx.x;
    if (row >= n) return;
    const float4* hr = (const float4*)(g_h + (size_t)row * 32);
    float o0 = sb[0], o1 = sb[1], o2 = sb[2];
#pragma unroll
    for (int k4 = 0; k4 < 8; k4++) {
        float4 v = hr[k4];
        o0 += v.x * sW[(4 * k4 + 0) * 3 + 0] + v.y * sW[(4 * k4 + 1) * 3 + 0] +
              v.z * sW[(4 * k4 + 2) * 3 + 0] + v.w * sW[(4 * k4 + 3) * 3 + 0];
        o1 += v.x * sW[(4 * k4 + 0) * 3 + 1] + v.y * sW[(4 * k4 + 1) * 3 + 1] +
              v.z * sW[(4 * k4 + 2) * 3 + 1] + v.w * sW[(4 * k4 + 3) * 3 + 1];
        o2 += v.x * sW[(4 * k4 + 0) * 3 + 2] + v.y * sW[(4 * k4 + 1) * 3 + 2] +
              v.z * sW[(4 * k4 + 2) * 3 + 2] + v.w * sW[(4 * k4 + 3) * 3 + 2];
    }
    out[(size_t)row * 3 + 0] = o0;
    out[(size_t)row * 3 + 1] = o1;
    out[(size_t)row * 3 + 2] = o2;
}

// ---------------------------------------------------------------------------
extern "C" void kernel_launch(void* const* d_in, const int* in_sizes, int n_in,
                              void* d_out, int out_size) {
    const float* x  = (const float*)d_in[0];
    const int*   ei = (const int*)d_in[1];
    const float* W1 = (const float*)d_in[2];
    const float* b1 = (const float*)d_in[3];
    const float* W2 = (const float*)d_in[4];
    const float* b2 = (const float*)d_in[5];
    const float* W3 = (const float*)d_in[6];
    const float* b3 = (const float*)d_in[7];
    const float* W4 = (const float*)d_in[8];
    const float* b4 = (const float*)d_in[9];
    const float* Wh = (const float*)d_in[10];
    const float* bh = (const float*)d_in[11];
    float* out = (float*)d_out;

    int n = in_sizes[0] / 128;  // 100000
    int e = in_sizes[1] / 2;    // 1600000
    const int* src = ei;
    const int* dst = ei + e;

    // device pointer to g_h (can't take &__device__ var from host)
    void* gh_ptr = nullptr;
    cudaGetSymbolAddress(&gh_ptr, g_h);
    const float* gh = (const float*)gh_ptr;

    const int B = 256;
    int gn = (n + B - 1) / B;
    int ge = (e + B - 1) / B;

    // normalization
    k_deg_init<<<gn, B>>>(n);
    k_deg_count<<<ge, B>>>(dst, e);
    k_deg_rsqrt<<<gn, B>>>(n);
    k_zero_acc<<<(n * 16 + B - 1) / B, B>>>(n * 16);

    // layer 1: 128 -> 64
    k_transform<128, 64><<<gn, B>>>(x, W1, n);
    k_scatter<64><<<(e * 16 + B - 1) / B, B>>>(src, dst, e);
    k_finish<64><<<(n * 16 + B - 1) / B, B>>>(b1, n);

    // layer 2: 64 -> 64
    k_transform<64, 64><<<gn, B>>>(gh, W2, n);
    k_scatter<64><<<(e * 16 + B - 1) / B, B>>>(src, dst, e);
    k_finish<64><<<(n * 16 + B - 1) / B, B>>>(b2, n);

    // layer 3: 64 -> 64
    k_transform<64, 64><<<gn, B>>>(gh, W3, n);
    k_scatter<64><<<(e * 16 + B - 1) / B, B>>>(src, dst, e);
    k_finish<64><<<(n * 16 + B - 1) / B, B>>>(b3, n);

    // layer 4: 64 -> 32
    k_transform<64, 32><<<gn, B>>>(gh, W4, n);
    k_scatter<32><<<(e * 8 + B - 1) / B, B>>>(src, dst, e);
    k_finish<32><<<(n * 8 + B - 1) / B, B>>>(b4, n);

    // head: 32 -> 3
    k_head<<<gn, B>>>(Wh, bh, out, n);
}

// round 2
// speedup vs baseline: 1.7067x; 1.7067x over previous
#include <cuda_runtime.h>

// Problem constants (fixed by the dataset)
#define NN 100000
#define EE 1600000
#define SCAN_B 256
#define NBLK ((NN + SCAN_B - 1) / SCAN_B)   // 391

// Scratch (allocation-free rule: __device__ globals)
__device__ float g_dinv[NN];
__device__ int   g_cnt[NN];
__device__ int   g_tmp[NN];          // per-block exclusive prefix
__device__ int   g_blk[512];         // block sums
__device__ int   g_rowstart[NN + 1];
__device__ int   g_cursor[NN];
__device__ int   g_csrc[EE];         // edge sources grouped by dst (CSR)
__device__ float g_u[(size_t)NN * 64];
__device__ float g_h[(size_t)NN * 64];

// ---------------------------------------------------------------------------
// packed f32x2 helpers (sm_103a)
// ---------------------------------------------------------------------------
__device__ __forceinline__ unsigned long long pack2(float a) {
    unsigned long long r;
    asm("mov.b64 %0, {%1, %1};" : "=l"(r) : "r"(__float_as_uint(a)));
    return r;
}
__device__ __forceinline__ void fma2(unsigned long long& d,
                                     unsigned long long a, unsigned long long b) {
    asm("fma.rn.f32x2 %0, %1, %2, %0;" : "+l"(d) : "l"(a), "l"(b));
}
__device__ __forceinline__ void mul2(unsigned long long& d, unsigned long long a) {
    asm("mul.rn.f32x2 %0, %1, %0;" : "+l"(d) : "l"(a));
}

// ---------------------------------------------------------------------------
// CSR build: histogram -> scan -> placement  (also produces dinv)
// ---------------------------------------------------------------------------
__global__ void k_hist_zero(int n) {
    int i = blockIdx.x * blockDim.x + threadIdx.x;
    if (i < n) g_cnt[i] = 0;
}

__global__ void k_hist(const int* __restrict__ dst, int e) {
    int i = blockIdx.x * blockDim.x + threadIdx.x;
    if (i < e) atomicAdd(&g_cnt[dst[i]], 1);
}

__global__ void k_dinv(int n) {
    int i = blockIdx.x * blockDim.x + threadIdx.x;
    if (i < n) g_dinv[i] = rsqrtf((float)(g_cnt[i] + 1));  // +1 self-loop
}

__global__ void k_scan_block(int n) {
    __shared__ int s[SCAN_B];
    int i = blockIdx.x * SCAN_B + threadIdx.x;
    int v = (i < n) ? g_cnt[i] : 0;
    s[threadIdx.x] = v;
    __syncthreads();
    for (int o = 1; o < SCAN_B; o <<= 1) {
        int t = (threadIdx.x >= o) ? s[threadIdx.x - o] : 0;
        __syncthreads();
        s[threadIdx.x] += t;
        __syncthreads();
    }
    if (i < n) g_tmp[i] = s[threadIdx.x] - v;          // exclusive within block
    if (threadIdx.x == SCAN_B - 1) g_blk[blockIdx.x] = s[SCAN_B - 1];
}

__global__ void k_scan_blk(int nb) {
    __shared__ int s[512];
    int t = threadIdx.x;
    int v = (t < nb) ? g_blk[t] : 0;
    s[t] = v;
    __syncthreads();
    for (int o = 1; o < 512; o <<= 1) {
        int w = (t >= o) ? s[t - o] : 0;
        __syncthreads();
        s[t] += w;
        __syncthreads();
    }
    if (t < nb) g_blk[t] = s[t] - v;                   // exclusive block offsets
}

__global__ void k_scan_add(int n, int e) {
    int i = blockIdx.x * SCAN_B + threadIdx.x;
    if (i < n) {
        int r = g_tmp[i] + g_blk[blockIdx.x];
        g_rowstart[i] = r;
        g_cursor[i] = r;
        if (i == n - 1) g_rowstart[n] = e;
    }
}

__global__ void k_place(const int* __restrict__ src, const int* __restrict__ dst, int e) {
    int i = blockIdx.x * blockDim.x + threadIdx.x;
    if (i < e) {
        int d = dst[i];
        int idx = atomicAdd(&g_cursor[d], 1);
        g_csrc[idx] = src[i];
    }
}

// ---------------------------------------------------------------------------
// Dense transform:  u[row] = dinv[row] * (hin[row] @ W)
// One thread per node row; W in shared (broadcast LDS); fma.rn.f32x2 packed.
// ---------------------------------------------------------------------------
template <int IN, int OUT>
__global__ void k_transform(const float* __restrict__ hin,
                            const float* __restrict__ W, int n) {
    __shared__ float sW[IN * OUT];
    for (int i = threadIdx.x; i < IN * OUT / 4; i += blockDim.x)
        ((float4*)sW)[i] = ((const float4*)W)[i];
    __syncthreads();

    int row = blockIdx.x * blockDim.x + threadIdx.x;
    if (row >= n) return;

    unsigned long long acc[OUT / 2];
#pragma unroll
    for (int c = 0; c < OUT / 2; c++) acc[c] = 0ull;

    const float4* hr = (const float4*)(hin + (size_t)row * IN);
#pragma unroll 1
    for (int k4 = 0; k4 < IN / 4; k4++) {
        float4 xv = hr[k4];
        float xs[4] = {xv.x, xv.y, xv.z, xv.w};
#pragma unroll
        for (int kk = 0; kk < 4; kk++) {
            unsigned long long xx = pack2(xs[kk]);
            const ulonglong2* wr = (const ulonglong2*)(sW + (k4 * 4 + kk) * OUT);
#pragma unroll
            for (int c4 = 0; c4 < OUT / 4; c4++) {
                ulonglong2 w = wr[c4];        // = packed(Wk[4c],Wk[4c+1]),(Wk[4c+2],Wk[4c+3])
                fma2(acc[2 * c4 + 0], xx, w.x);
                fma2(acc[2 * c4 + 1], xx, w.y);
            }
        }
    }

    unsigned long long dd = pack2(g_dinv[row]);
    ulonglong2* ur = (ulonglong2*)(g_u + (size_t)row * OUT);
#pragma unroll
    for (int c4 = 0; c4 < OUT / 4; c4++) {
        ulonglong2 o;
        o.x = acc[2 * c4 + 0];
        o.y = acc[2 * c4 + 1];
        mul2(o.x, dd);
        mul2(o.y, dd);
        ur[c4] = o;
    }
}

// ---------------------------------------------------------------------------
// Fused aggregate + finish:
//   h[i] = relu(dinv[i] * (u[i] + sum_{j in N(i)} u[j]) + b)
// OUT/4 threads cooperate per node; CSR gather, register accumulation.
// ---------------------------------------------------------------------------
template <int OUT>
__global__ void k_aggregate(const float* __restrict__ b, float* __restrict__ hout, int n) {
    constexpr int C4 = OUT / 4;
    int t = blockIdx.x * blockDim.x + threadIdx.x;
    int node = t / C4;
    int c4 = t - node * C4;
    if (node >= n) return;

    int s0 = g_rowstart[node];
    int s1 = g_rowstart[node + 1];
    const float4* u4 = (const float4*)g_u;

    float4 a = u4[(size_t)node * C4 + c4];  // self-loop term
    int k = s0;
    int snext = (k < s1) ? g_csrc[k] : 0;
    while (k < s1) {
        int scur = snext;
        k++;
        snext = (k < s1) ? g_csrc[k] : 0;   // prefetch next index
        float4 v = u4[(size_t)scur * C4 + c4];
        a.x += v.x; a.y += v.y; a.z += v.z; a.w += v.w;
    }

    float dv = g_dinv[node];
    float4 bb = ((const float4*)b)[c4];
    float4 r;
    r.x = fmaxf(fmaf(dv, a.x, bb.x), 0.f);
    r.y = fmaxf(fmaf(dv, a.y, bb.y), 0.f);
    r.z = fmaxf(fmaf(dv, a.z, bb.z), 0.f);
    r.w = fmaxf(fmaf(dv, a.w, bb.w), 0.f);
    ((float4*)hout)[(size_t)node * C4 + c4] = r;
}

// ---------------------------------------------------------------------------
// Head: out[row] = h(32) @ Wh(32x3) + bh
// ---------------------------------------------------------------------------
__global__ void k_head(const float* __restrict__ Wh, const float* __restrict__ bh,
                       float* __restrict__ out, int n) {
    __shared__ float sW[96];
    __shared__ float sb[3];
    if (threadIdx.x < 96) sW[threadIdx.x] = Wh[threadIdx.x];
    if (threadIdx.x < 3) sb[threadIdx.x] = bh[threadIdx.x];
    __syncthreads();
    int row = blockIdx.x * blockDim.x + threadIdx.x;
    if (row >= n) return;
    const float4* hr = (const float4*)(g_h + (size_t)row * 32);
    float o0 = sb[0], o1 = sb[1], o2 = sb[2];
#pragma unroll
    for (int k4 = 0; k4 < 8; k4++) {
        float4 v = hr[k4];
        o0 += v.x * sW[(4 * k4 + 0) * 3 + 0] + v.y * sW[(4 * k4 + 1) * 3 + 0] +
              v.z * sW[(4 * k4 + 2) * 3 + 0] + v.w * sW[(4 * k4 + 3) * 3 + 0];
        o1 += v.x * sW[(4 * k4 + 0) * 3 + 1] + v.y * sW[(4 * k4 + 1) * 3 + 1] +
              v.z * sW[(4 * k4 + 2) * 3 + 1] + v.w * sW[(4 * k4 + 3) * 3 + 1];
        o2 += v.x * sW[(4 * k4 + 0) * 3 + 2] + v.y * sW[(4 * k4 + 1) * 3 + 2] +
              v.z * sW[(4 * k4 + 2) * 3 + 2] + v.w * sW[(4 * k4 + 3) * 3 + 2];
    }
    out[(size_t)row * 3 + 0] = o0;
    out[(size_t)row * 3 + 1] = o1;
    out[(size_t)row * 3 + 2] = o2;
}

// ---------------------------------------------------------------------------
extern "C" void kernel_launch(void* const* d_in, const int* in_sizes, int n_in,
                              void* d_out, int out_size) {
    const float* x  = (const float*)d_in[0];
    const int*   ei = (const int*)d_in[1];
    const float* W1 = (const float*)d_in[2];
    const float* b1 = (const float*)d_in[3];
    const float* W2 = (const float*)d_in[4];
    const float* b2 = (const float*)d_in[5];
    const float* W3 = (const float*)d_in[6];
    const float* b3 = (const float*)d_in[7];
    const float* W4 = (const float*)d_in[8];
    const float* b4 = (const float*)d_in[9];
    const float* Wh = (const float*)d_in[10];
    const float* bh = (const float*)d_in[11];
    float* out = (float*)d_out;

    int n = in_sizes[0] / 128;  // 100000
    int e = in_sizes[1] / 2;    // 1600000
    const int* src = ei;
    const int* dst = ei + e;

    void* gh_ptr = nullptr;
    cudaGetSymbolAddress(&gh_ptr, g_h);
    float* gh = (float*)gh_ptr;

    const int B = 256;
    int gn = (n + B - 1) / B;
    int ge = (e + B - 1) / B;

    // CSR build + normalization
    k_hist_zero<<<gn, B>>>(n);
    k_hist<<<ge, B>>>(dst, e);
    k_dinv<<<gn, B>>>(n);
    k_scan_block<<<NBLK, SCAN_B>>>(n);
    k_scan_blk<<<1, 512>>>(NBLK);
    k_scan_add<<<NBLK, SCAN_B>>>(n, e);
    k_place<<<ge, B>>>(src, dst, e);

    // layer 1: 128 -> 64
    k_transform<128, 64><<<gn, B>>>(x, W1, n);
    k_aggregate<64><<<(n * 16 + B - 1) / B, B>>>(b1, gh, n);

    // layer 2: 64 -> 64
    k_transform<64, 64><<<gn, B>>>(gh, W2, n);
    k_aggregate<64><<<(n * 16 + B - 1) / B, B>>>(b2, gh, n);

    // layer 3: 64 -> 64
    k_transform<64, 64><<<gn, B>>>(gh, W3, n);
    k_aggregate<64><<<(n * 16 + B - 1) / B, B>>>(b3, gh, n);

    // layer 4: 64 -> 32
    k_transform<64, 32><<<gn, B>>>(gh, W4, n);
    k_aggregate<32><<<(n * 8 + B - 1) / B, B>>>(b4, gh, n);

    // head: 32 -> 3
    k_head<<<gn, B>>>(Wh, bh, out, n);
}

// round 3
// speedup vs baseline: 1.7165x; 1.0057x over previous
#include <cuda_runtime.h>

// Problem constants (fixed by the dataset)
#define NN 100000
#define EE 1600000
#define SCAN_B 256
#define NBLK ((NN + SCAN_B - 1) / SCAN_B)   // 391

// Scratch (allocation-free rule: __device__ globals)
__device__ float g_dinv[NN];
__device__ int   g_cnt[NN];
__device__ int   g_tmp[NN];          // per-block exclusive prefix
__device__ int   g_blk[512];         // block sums
__device__ int   g_rowstart[NN + 1];
__device__ int   g_cursor[NN];
__device__ int   g_csrc[EE];         // edge sources grouped by dst (CSR)
__device__ float g_u[(size_t)NN * 64];
__device__ float g_h[(size_t)NN * 64];

// ---------------------------------------------------------------------------
// packed f32x2 helpers (sm_103a)
// ---------------------------------------------------------------------------
__device__ __forceinline__ unsigned long long pack2(float a) {
    unsigned long long r;
    asm("mov.b64 %0, {%1, %1};" : "=l"(r) : "r"(__float_as_uint(a)));
    return r;
}
__device__ __forceinline__ void fma2(unsigned long long& d,
                                     unsigned long long a, unsigned long long b) {
    asm("fma.rn.f32x2 %0, %1, %2, %0;" : "+l"(d) : "l"(a), "l"(b));
}
__device__ __forceinline__ void mul2(unsigned long long& d, unsigned long long a) {
    asm("mul.rn.f32x2 %0, %1, %0;" : "+l"(d) : "l"(a));
}

// ---------------------------------------------------------------------------
// CSR build: histogram -> scan -> placement  (also produces dinv)
// ---------------------------------------------------------------------------
__global__ void k_hist_zero(int n) {
    int i = blockIdx.x * blockDim.x + threadIdx.x;
    if (i < n) g_cnt[i] = 0;
}

__global__ void k_hist(const int* __restrict__ dst, int e4) {
    int i = blockIdx.x * blockDim.x + threadIdx.x;
    if (i < e4) {
        int4 d = ((const int4*)dst)[i];
        atomicAdd(&g_cnt[d.x], 1);
        atomicAdd(&g_cnt[d.y], 1);
        atomicAdd(&g_cnt[d.z], 1);
        atomicAdd(&g_cnt[d.w], 1);
    }
}

__global__ void k_dinv(int n) {
    int i = blockIdx.x * blockDim.x + threadIdx.x;
    if (i < n) g_dinv[i] = rsqrtf((float)(g_cnt[i] + 1));  // +1 self-loop
}

__global__ void k_scan_block(int n) {
    __shared__ int s[SCAN_B];
    int i = blockIdx.x * SCAN_B + threadIdx.x;
    int v = (i < n) ? g_cnt[i] : 0;
    s[threadIdx.x] = v;
    __syncthreads();
    for (int o = 1; o < SCAN_B; o <<= 1) {
        int t = (threadIdx.x >= o) ? s[threadIdx.x - o] : 0;
        __syncthreads();
        s[threadIdx.x] += t;
        __syncthreads();
    }
    if (i < n) g_tmp[i] = s[threadIdx.x] - v;          // exclusive within block
    if (threadIdx.x == SCAN_B - 1) g_blk[blockIdx.x] = s[SCAN_B - 1];
}

__global__ void k_scan_blk(int nb) {
    __shared__ int s[512];
    int t = threadIdx.x;
    int v = (t < nb) ? g_blk[t] : 0;
    s[t] = v;
    __syncthreads();
    for (int o = 1; o < 512; o <<= 1) {
        int w = (t >= o) ? s[t - o] : 0;
        __syncthreads();
        s[t] += w;
        __syncthreads();
    }
    if (t < nb) g_blk[t] = s[t] - v;                   // exclusive block offsets
}

__global__ void k_scan_add(int n, int e) {
    int i = blockIdx.x * SCAN_B + threadIdx.x;
    if (i < n) {
        int r = g_tmp[i] + g_blk[blockIdx.x];
        g_rowstart[i] = r;
        g_cursor[i] = r;
        if (i == n - 1) g_rowstart[n] = e;
    }
}

__global__ void k_place(const int* __restrict__ src, const int* __restrict__ dst, int e4) {
    int i = blockIdx.x * blockDim.x + threadIdx.x;
    if (i < e4) {
        int4 s = ((const int4*)src)[i];
        int4 d = ((const int4*)dst)[i];
        g_csrc[atomicAdd(&g_cursor[d.x], 1)] = s.x;
        g_csrc[atomicAdd(&g_cursor[d.y], 1)] = s.y;
        g_csrc[atomicAdd(&g_cursor[d.z], 1)] = s.z;
        g_csrc[atomicAdd(&g_cursor[d.w], 1)] = s.w;
    }
}

// ---------------------------------------------------------------------------
// Dense transform:  u[row] = dinv[row] * (hin[row] @ W)
// One thread per node row; W in shared (broadcast LDS); fma.rn.f32x2 packed.
// ---------------------------------------------------------------------------
template <int IN, int OUT>
__global__ void k_transform(const float* __restrict__ hin,
                            const float* __restrict__ W, int n) {
    __shared__ float sW[IN * OUT];
    for (int i = threadIdx.x; i < IN * OUT / 4; i += blockDim.x)
        ((float4*)sW)[i] = ((const float4*)W)[i];
    __syncthreads();

    int row = blockIdx.x * blockDim.x + threadIdx.x;
    if (row >= n) return;

    unsigned long long acc[OUT / 2];
#pragma unroll
    for (int c = 0; c < OUT / 2; c++) acc[c] = 0ull;

    const float4* hr = (const float4*)(hin + (size_t)row * IN);
#pragma unroll 1
    for (int k4 = 0; k4 < IN / 4; k4++) {
        float4 xv = hr[k4];
        float xs[4] = {xv.x, xv.y, xv.z, xv.w};
#pragma unroll
        for (int kk = 0; kk < 4; kk++) {
            unsigned long long xx = pack2(xs[kk]);
            const ulonglong2* wr = (const ulonglong2*)(sW + (k4 * 4 + kk) * OUT);
#pragma unroll
            for (int c4 = 0; c4 < OUT / 4; c4++) {
                ulonglong2 w = wr[c4];
                fma2(acc[2 * c4 + 0], xx, w.x);
                fma2(acc[2 * c4 + 1], xx, w.y);
            }
        }
    }

    unsigned long long dd = pack2(g_dinv[row]);
    ulonglong2* ur = (ulonglong2*)(g_u + (size_t)row * OUT);
#pragma unroll
    for (int c4 = 0; c4 < OUT / 4; c4++) {
        ulonglong2 o;
        o.x = acc[2 * c4 + 0];
        o.y = acc[2 * c4 + 1];
        mul2(o.x, dd);
        mul2(o.y, dd);
        ur[c4] = o;
    }
}

// ---------------------------------------------------------------------------
// Core CSR gather-sum for one (node, c4) pair: 2-way unrolled, dual prefetch.
// ---------------------------------------------------------------------------
template <int C4>
__device__ __forceinline__ float4 gather_sum(int node, int c4) {
    int s0 = g_rowstart[node];
    int s1 = g_rowstart[node + 1];
    const float4* u4 = (const float4*)g_u;

    float4 a0 = u4[(size_t)node * C4 + c4];  // self-loop term
    float4 a1 = make_float4(0.f, 0.f, 0.f, 0.f);

    int k = s0;
    int i0 = (k < s1) ? g_csrc[k] : 0;
    int i1 = (k + 1 < s1) ? g_csrc[k + 1] : 0;
    while (k + 2 <= s1) {
        int j0 = i0, j1 = i1;
        i0 = (k + 2 < s1) ? g_csrc[k + 2] : 0;
        i1 = (k + 3 < s1) ? g_csrc[k + 3] : 0;
        float4 v0 = u4[(size_t)j0 * C4 + c4];
        float4 v1 = u4[(size_t)j1 * C4 + c4];
        a0.x += v0.x; a0.y += v0.y; a0.z += v0.z; a0.w += v0.w;
        a1.x += v1.x; a1.y += v1.y; a1.z += v1.z; a1.w += v1.w;
        k += 2;
    }
    if (k < s1) {
        float4 v = u4[(size_t)i0 * C4 + c4];
        a0.x += v.x; a0.y += v.y; a0.z += v.z; a0.w += v.w;
    }
    a0.x += a1.x; a0.y += a1.y; a0.z += a1.z; a0.w += a1.w;
    return a0;
}

// ---------------------------------------------------------------------------
// Fused aggregate + finish:
//   h[i] = relu(dinv[i] * (u[i] + sum_{j in N(i)} u[j]) + b)
// ---------------------------------------------------------------------------
template <int OUT>
__global__ void k_aggregate(const float* __restrict__ b, float* __restrict__ hout, int n) {
    constexpr int C4 = OUT / 4;
    int t = blockIdx.x * blockDim.x + threadIdx.x;
    int node = t / C4;
    int c4 = t - node * C4;
    if (node >= n) return;

    float4 a = gather_sum<C4>(node, c4);

    float dv = g_dinv[node];
    float4 bb = ((const float4*)b)[c4];
    float4 r;
    r.x = fmaxf(fmaf(dv, a.x, bb.x), 0.f);
    r.y = fmaxf(fmaf(dv, a.y, bb.y), 0.f);
    r.z = fmaxf(fmaf(dv, a.z, bb.z), 0.f);
    r.w = fmaxf(fmaf(dv, a.w, bb.w), 0.f);
    ((float4*)hout)[(size_t)node * C4 + c4] = r;
}

// ---------------------------------------------------------------------------
// Layer 4 aggregate fused with the output head:
//   h = relu(dinv*(agg)+b4)  (32 wide, 8 lanes/node)
//   out[node] = h @ Wh(32x3) + bh   via intra-warp shuffle reduce over 8 lanes
// ---------------------------------------------------------------------------
__global__ void k_aggregate_head(const float* __restrict__ b,
                                 const float* __restrict__ Wh,
                                 const float* __restrict__ bh,
                                 float* __restrict__ out, int n) {
    constexpr int C4 = 8;  // 32/4
    __shared__ float sW[96];
    __shared__ float sb[3];
    if (threadIdx.x < 96) sW[threadIdx.x] = Wh[threadIdx.x];
    if (threadIdx.x < 3) sb[threadIdx.x] = bh[threadIdx.x];
    __syncthreads();

    int t = blockIdx.x * blockDim.x + threadIdx.x;
    int node = t / C4;
    int c4 = t - node * C4;
    if (node >= n) return;  // n*8 divides 256 exactly -> whole warps exit together

    float4 a = gather_sum<C4>(node, c4);

    float dv = g_dinv[node];
    float4 bb = ((const float4*)b)[c4];
    float4 r;
    r.x = fmaxf(fmaf(dv, a.x, bb.x), 0.f);
    r.y = fmaxf(fmaf(dv, a.y, bb.y), 0.f);
    r.z = fmaxf(fmaf(dv, a.z, bb.z), 0.f);
    r.w = fmaxf(fmaf(dv, a.w, bb.w), 0.f);

    // head partials: this lane covers h cols [4*c4, 4*c4+3]
    float po[3];
#pragma unroll
    for (int j = 0; j < 3; j++) {
        po[j] = r.x * sW[(4 * c4 + 0) * 3 + j] + r.y * sW[(4 * c4 + 1) * 3 + j] +
                r.z * sW[(4 * c4 + 2) * 3 + j] + r.w * sW[(4 * c4 + 3) * 3 + j];
    }
    // reduce across the 8 lanes of this node
#pragma unroll
    for (int o = 4; o >= 1; o >>= 1) {
#pragma unroll
        for (int j = 0; j < 3; j++)
            po[j] += __shfl_down_sync(0xffffffffu, po[j], o, 8);
    }
    if (c4 == 0) {
        out[(size_t)node * 3 + 0] = po[0] + sb[0];
        out[(size_t)node * 3 + 1] = po[1] + sb[1];
        out[(size_t)node * 3 + 2] = po[2] + sb[2];
    }
}

// ---------------------------------------------------------------------------
extern "C" void kernel_launch(void* const* d_in, const int* in_sizes, int n_in,
                              void* d_out, int out_size) {
    const float* x  = (const float*)d_in[0];
    const int*   ei = (const int*)d_in[1];
    const float* W1 = (const float*)d_in[2];
    const float* b1 = (const float*)d_in[3];
    const float* W2 = (const float*)d_in[4];
    const float* b2 = (const float*)d_in[5];
    const float* W3 = (const float*)d_in[6];
    const float* b3 = (const float*)d_in[7];
    const float* W4 = (const float*)d_in[8];
    const float* b4 = (const float*)d_in[9];
    const float* Wh = (const float*)d_in[10];
    const float* bh = (const float*)d_in[11];
    float* out = (float*)d_out;

    int n = in_sizes[0] / 128;  // 100000
    int e = in_sizes[1] / 2;    // 1600000
    const int* src = ei;
    const int* dst = ei + e;

    void* gh_ptr = nullptr;
    cudaGetSymbolAddress(&gh_ptr, g_h);
    float* gh = (float*)gh_ptr;

    const int B = 256;
    int gn = (n + B - 1) / B;
    int e4 = e / 4;
    int ge4 = (e4 + B - 1) / B;

    // --- CSR prologue, ordered so launch #4 (the ncu sample) is transform1 ---
    k_hist_zero<<<gn, B>>>(n);                       // 1
    k_hist<<<ge4, B>>>(dst, e4);                     // 2
    k_dinv<<<gn, B>>>(n);                            // 3
    k_transform<128, 64><<<gn, B>>>(x, W1, n);       // 4  <- profiled
    k_scan_block<<<NBLK, SCAN_B>>>(n);               // 5
    k_scan_blk<<<1, 512>>>(NBLK);                    // 6
    k_scan_add<<<NBLK, SCAN_B>>>(n, e);              // 7
    k_place<<<ge4, B>>>(src, dst, e4);               // 8

    // layer 1 aggregate (transform already done above)
    k_aggregate<64><<<(n * 16 + B - 1) / B, B>>>(b1, gh, n);

    // layer 2: 64 -> 64
    k_transform<64, 64><<<gn, B>>>(gh, W2, n);
    k_aggregate<64><<<(n * 16 + B - 1) / B, B>>>(b2, gh, n);

    // layer 3: 64 -> 64
    k_transform<64, 64><<<gn, B>>>(gh, W3, n);
    k_aggregate<64><<<(n * 16 + B - 1) / B, B>>>(b3, gh, n);

    // layer 4: 64 -> 32, aggregate fused with head
    k_transform<64, 32><<<gn, B>>>(gh, W4, n);
    k_aggregate_head<<<(n * 8 + B - 1) / B, B>>>(b4, Wh, bh, out, n);
}

// round 4
// speedup vs baseline: 1.8544x; 1.0804x over previous
#include <cuda_runtime.h>

// Problem constants (fixed by the dataset)
#define NN 100000
#define EE 1600000
#define SCAN_B 256
#define NBLK ((NN + SCAN_B - 1) / SCAN_B)   // 391

// Scratch (allocation-free rule: __device__ globals)
__device__ float g_dinv[NN];
__device__ int   g_cnt[NN];
__device__ int   g_tmp[NN];
__device__ int   g_blk[512];
__device__ int   g_rowstart[NN + 1];
__device__ int   g_cursor[NN];
__device__ int   g_csrc[EE];
__device__ float g_u[(size_t)NN * 64];
__device__ float g_h[(size_t)NN * 64];

// ---------------------------------------------------------------------------
// packed f32x2 helpers (sm_103a)
// ---------------------------------------------------------------------------
__device__ __forceinline__ unsigned long long pack2(float a) {
    unsigned long long r;
    asm("mov.b64 %0, {%1, %1};" : "=l"(r) : "r"(__float_as_uint(a)));
    return r;
}
__device__ __forceinline__ void fma2(unsigned long long& d,
                                     unsigned long long a, unsigned long long b) {
    asm("fma.rn.f32x2 %0, %1, %2, %0;" : "+l"(d) : "l"(a), "l"(b));
}
__device__ __forceinline__ void mul2(unsigned long long& d, unsigned long long a) {
    asm("mul.rn.f32x2 %0, %1, %0;" : "+l"(d) : "l"(a));
}

// ---------------------------------------------------------------------------
// CSR build
// ---------------------------------------------------------------------------
__global__ void k_hist_zero(int n) {
    int i = blockIdx.x * blockDim.x + threadIdx.x;
    if (i < n) g_cnt[i] = 0;
}

__global__ void k_hist(const int* __restrict__ dst, int e4) {
    int i = blockIdx.x * blockDim.x + threadIdx.x;
    if (i < e4) {
        int4 d = ((const int4*)dst)[i];
        atomicAdd(&g_cnt[d.x], 1);
        atomicAdd(&g_cnt[d.y], 1);
        atomicAdd(&g_cnt[d.z], 1);
        atomicAdd(&g_cnt[d.w], 1);
    }
}

// block-local scan of cnt; also produces dinv (fused)
__global__ void k_scan_block(int n) {
    __shared__ int s[SCAN_B];
    int i = blockIdx.x * SCAN_B + threadIdx.x;
    int v = (i < n) ? g_cnt[i] : 0;
    if (i < n) g_dinv[i] = rsqrtf((float)(v + 1));  // +1 self-loop
    s[threadIdx.x] = v;
    __syncthreads();
    for (int o = 1; o < SCAN_B; o <<= 1) {
        int t = (threadIdx.x >= o) ? s[threadIdx.x - o] : 0;
        __syncthreads();
        s[threadIdx.x] += t;
        __syncthreads();
    }
    if (i < n) g_tmp[i] = s[threadIdx.x] - v;
    if (threadIdx.x == SCAN_B - 1) g_blk[blockIdx.x] = s[SCAN_B - 1];
}

__global__ void k_scan_blk(int nb) {
    __shared__ int s[512];
    int t = threadIdx.x;
    int v = (t < nb) ? g_blk[t] : 0;
    s[t] = v;
    __syncthreads();
    for (int o = 1; o < 512; o <<= 1) {
        int w = (t >= o) ? s[t - o] : 0;
        __syncthreads();
        s[t] += w;
        __syncthreads();
    }
    if (t < nb) g_blk[t] = s[t] - v;
}

__global__ void k_scan_add(int n, int e) {
    int i = blockIdx.x * SCAN_B + threadIdx.x;
    if (i < n) {
        int r = g_tmp[i] + g_blk[blockIdx.x];
        g_rowstart[i] = r;
        g_cursor[i] = r;
        if (i == n - 1) g_rowstart[n] = e;
    }
}

__global__ void k_place(const int* __restrict__ src, const int* __restrict__ dst, int e4) {
    int i = blockIdx.x * blockDim.x + threadIdx.x;
    if (i < e4) {
        int4 s = ((const int4*)src)[i];
        int4 d = ((const int4*)dst)[i];
        g_csrc[atomicAdd(&g_cursor[d.x], 1)] = s.x;
        g_csrc[atomicAdd(&g_cursor[d.y], 1)] = s.y;
        g_csrc[atomicAdd(&g_cursor[d.z], 1)] = s.z;
        g_csrc[atomicAdd(&g_cursor[d.w], 1)] = s.w;
    }
}

// ---------------------------------------------------------------------------
// Dense transform with 4x register blocking:
//   u[row] = dinv[row] * (hin[row] @ W)
// Each thread computes a 4-row x (OUT/4)-col tile: one shared W read feeds
// 4 rows -> LDS traffic cut 4x vs one-row-per-thread.
// Thread mapping: gid -> (rq = gid>>2 row quad, cg = gid&3 column group).
// Rows rq, rq+q, rq+2q, rq+3q  (q = ceil(n/4)).
// ---------------------------------------------------------------------------
template <int IN, int OUT>
__global__ void k_transform(const float* __restrict__ hin,
                            const float* __restrict__ W, int n, int q) {
    constexpr int COLS = OUT / 4;   // cols per thread
    constexpr int P = COLS / 2;     // u64 accumulators per row
    __shared__ float sW[IN * OUT];
    for (int i = threadIdx.x; i < IN * OUT / 4; i += blockDim.x)
        ((float4*)sW)[i] = ((const float4*)W)[i];
    __syncthreads();

    int gid = blockIdx.x * blockDim.x + threadIdx.x;
    int cg = gid & 3;
    int rq = gid >> 2;
    if (rq >= q) return;

    int r0 = rq, r1 = rq + q, r2 = rq + 2 * q, r3 = rq + 3 * q;
    bool v1 = r1 < n, v2 = r2 < n, v3 = r3 < n;
    const float4* h0 = (const float4*)(hin + (size_t)r0 * IN);
    const float4* h1 = (const float4*)(hin + (size_t)(v1 ? r1 : r0) * IN);
    const float4* h2 = (const float4*)(hin + (size_t)(v2 ? r2 : r0) * IN);
    const float4* h3 = (const float4*)(hin + (size_t)(v3 ? r3 : r0) * IN);

    unsigned long long acc[4][P];
#pragma unroll
    for (int r = 0; r < 4; r++)
#pragma unroll
        for (int c = 0; c < P; c++) acc[r][c] = 0ull;

    const float* wbase = sW + cg * COLS;

#pragma unroll 1
    for (int k4 = 0; k4 < IN / 4; k4++) {
        float4 x0 = h0[k4], x1 = h1[k4], x2 = h2[k4], x3 = h3[k4];
        float xa0[4] = {x0.x, x0.y, x0.z, x0.w};
        float xa1[4] = {x1.x, x1.y, x1.z, x1.w};
        float xa2[4] = {x2.x, x2.y, x2.z, x2.w};
        float xa3[4] = {x3.x, x3.y, x3.z, x3.w};
#pragma unroll
        for (int kk = 0; kk < 4; kk++) {
            const ulonglong2* wr = (const ulonglong2*)(wbase + (k4 * 4 + kk) * OUT);
            unsigned long long p0 = pack2(xa0[kk]);
            unsigned long long p1 = pack2(xa1[kk]);
            unsigned long long p2 = pack2(xa2[kk]);
            unsigned long long p3 = pack2(xa3[kk]);
#pragma unroll
            for (int c = 0; c < P / 2; c++) {
                ulonglong2 w = wr[c];
                fma2(acc[0][2 * c + 0], p0, w.x);
                fma2(acc[0][2 * c + 1], p0, w.y);
                fma2(acc[1][2 * c + 0], p1, w.x);
                fma2(acc[1][2 * c + 1], p1, w.y);
                fma2(acc[2][2 * c + 0], p2, w.x);
                fma2(acc[2][2 * c + 1], p2, w.y);
                fma2(acc[3][2 * c + 0], p3, w.x);
                fma2(acc[3][2 * c + 1], p3, w.y);
            }
        }
    }

    int rows[4] = {r0, r1, r2, r3};
    bool vv[4] = {true, v1, v2, v3};
#pragma unroll
    for (int r = 0; r < 4; r++) {
        if (!vv[r]) continue;
        unsigned long long dd = pack2(g_dinv[rows[r]]);
        ulonglong2* ur = (ulonglong2*)(g_u + (size_t)rows[r] * OUT + cg * COLS);
#pragma unroll
        for (int c = 0; c < P / 2; c++) {
            ulonglong2 o;
            o.x = acc[r][2 * c + 0];
            o.y = acc[r][2 * c + 1];
            mul2(o.x, dd);
            mul2(o.y, dd);
            ur[c] = o;
        }
    }
}

// ---------------------------------------------------------------------------
// CSR gather-sum for one (node, c4): 4-way unrolled, quad index prefetch.
// ---------------------------------------------------------------------------
template <int C4>
__device__ __forceinline__ float4 gather_sum(int node, int c4) {
    int s0 = g_rowstart[node];
    int s1 = g_rowstart[node + 1];
    const float4* u4 = (const float4*)g_u;

    float4 a0 = u4[(size_t)node * C4 + c4];  // self-loop term
    float4 a1 = make_float4(0.f, 0.f, 0.f, 0.f);
    float4 a2 = make_float4(0.f, 0.f, 0.f, 0.f);
    float4 a3 = make_float4(0.f, 0.f, 0.f, 0.f);

    int k = s0;
    int i0 = (k + 0 < s1) ? g_csrc[k + 0] : 0;
    int i1 = (k + 1 < s1) ? g_csrc[k + 1] : 0;
    int i2 = (k + 2 < s1) ? g_csrc[k + 2] : 0;
    int i3 = (k + 3 < s1) ? g_csrc[k + 3] : 0;
    while (k + 4 <= s1) {
        int j0 = i0, j1 = i1, j2 = i2, j3 = i3;
        i0 = (k + 4 < s1) ? g_csrc[k + 4] : 0;
        i1 = (k + 5 < s1) ? g_csrc[k + 5] : 0;
        i2 = (k + 6 < s1) ? g_csrc[k + 6] : 0;
        i3 = (k + 7 < s1) ? g_csrc[k + 7] : 0;
        float4 v0 = u4[(size_t)j0 * C4 + c4];
        float4 v1 = u4[(size_t)j1 * C4 + c4];
        float4 v2 = u4[(size_t)j2 * C4 + c4];
        float4 v3 = u4[(size_t)j3 * C4 + c4];
        a0.x += v0.x; a0.y += v0.y; a0.z += v0.z; a0.w += v0.w;
        a1.x += v1.x; a1.y += v1.y; a1.z += v1.z; a1.w += v1.w;
        a2.x += v2.x; a2.y += v2.y; a2.z += v2.z; a2.w += v2.w;
        a3.x += v3.x; a3.y += v3.y; a3.z += v3.z; a3.w += v3.w;
        k += 4;
    }
    if (k + 0 < s1) { float4 v = u4[(size_t)i0 * C4 + c4]; a0.x += v.x; a0.y += v.y; a0.z += v.z; a0.w += v.w; }
    if (k + 1 < s1) { float4 v = u4[(size_t)i1 * C4 + c4]; a1.x += v.x; a1.y += v.y; a1.z += v.z; a1.w += v.w; }
    if (k + 2 < s1) { float4 v = u4[(size_t)i2 * C4 + c4]; a2.x += v.x; a2.y += v.y; a2.z += v.z; a2.w += v.w; }
    a0.x += a1.x + a2.x + a3.x;
    a0.y += a1.y + a2.y + a3.y;
    a0.z += a1.z + a2.z + a3.z;
    a0.w += a1.w + a2.w + a3.w;
    return a0;
}

// ---------------------------------------------------------------------------
// Fused aggregate + finish
// ---------------------------------------------------------------------------
template <int OUT>
__global__ void k_aggregate(const float* __restrict__ b, float* __restrict__ hout, int n) {
    constexpr int C4 = OUT / 4;
    int t = blockIdx.x * blockDim.x + threadIdx.x;
    int node = t / C4;
    int c4 = t - node * C4;
    if (node >= n) return;

    float4 a = gather_sum<C4>(node, c4);

    float dv = g_dinv[node];
    float4 bb = ((const float4*)b)[c4];
    float4 r;
    r.x = fmaxf(fmaf(dv, a.x, bb.x), 0.f);
    r.y = fmaxf(fmaf(dv, a.y, bb.y), 0.f);
    r.z = fmaxf(fmaf(dv, a.z, bb.z), 0.f);
    r.w = fmaxf(fmaf(dv, a.w, bb.w), 0.f);
    ((float4*)hout)[(size_t)node * C4 + c4] = r;
}

// ---------------------------------------------------------------------------
// Layer-4 aggregate fused with the output head
// ---------------------------------------------------------------------------
__global__ void k_aggregate_head(const float* __restrict__ b,
                                 const float* __restrict__ Wh,
                                 const float* __restrict__ bh,
                                 float* __restrict__ out, int n) {
    constexpr int C4 = 8;  // 32/4
    __shared__ float sW[96];
    __shared__ float sb[3];
    if (threadIdx.x < 96) sW[threadIdx.x] = Wh[threadIdx.x];
    if (threadIdx.x < 3) sb[threadIdx.x] = bh[threadIdx.x];
    __syncthreads();

    int t = blockIdx.x * blockDim.x + threadIdx.x;
    int node = t / C4;
    int c4 = t - node * C4;
    if (node >= n) return;

    float4 a = gather_sum<C4>(node, c4);

    float dv = g_dinv[node];
    float4 bb = ((const float4*)b)[c4];
    float4 r;
    r.x = fmaxf(fmaf(dv, a.x, bb.x), 0.f);
    r.y = fmaxf(fmaf(dv, a.y, bb.y), 0.f);
    r.z = fmaxf(fmaf(dv, a.z, bb.z), 0.f);
    r.w = fmaxf(fmaf(dv, a.w, bb.w), 0.f);

    float po[3];
#pragma unroll
    for (int j = 0; j < 3; j++) {
        po[j] = r.x * sW[(4 * c4 + 0) * 3 + j] + r.y * sW[(4 * c4 + 1) * 3 + j] +
                r.z * sW[(4 * c4 + 2) * 3 + j] + r.w * sW[(4 * c4 + 3) * 3 + j];
    }
#pragma unroll
    for (int o = 4; o >= 1; o >>= 1) {
#pragma unroll
        for (int j = 0; j < 3; j++)
            po[j] += __shfl_down_sync(0xffffffffu, po[j], o, 8);
    }
    if (c4 == 0) {
        out[(size_t)node * 3 + 0] = po[0] + sb[0];
        out[(size_t)node * 3 + 1] = po[1] + sb[1];
        out[(size_t)node * 3 + 2] = po[2] + sb[2];
    }
}

// ---------------------------------------------------------------------------
extern "C" void kernel_launch(void* const* d_in, const int* in_sizes, int n_in,
                              void* d_out, int out_size) {
    const float* x  = (const float*)d_in[0];
    const int*   ei = (const int*)d_in[1];
    const float* W1 = (const float*)d_in[2];
    const float* b1 = (const float*)d_in[3];
    const float* W2 = (const float*)d_in[4];
    const float* b2 = (const float*)d_in[5];
    const float* W3 = (const float*)d_in[6];
    const float* b3 = (const float*)d_in[7];
    const float* W4 = (const float*)d_in[8];
    const float* b4 = (const float*)d_in[9];
    const float* Wh = (const float*)d_in[10];
    const float* bh = (const float*)d_in[11];
    float* out = (float*)d_out;

    int n = in_sizes[0] / 128;  // 100000
    int e = in_sizes[1] / 2;    // 1600000
    const int* src = ei;
    const int* dst = ei + e;

    void* gh_ptr = nullptr;
    cudaGetSymbolAddress(&gh_ptr, g_h);
    float* gh = (float*)gh_ptr;

    const int B = 256;
    int gn = (n + B - 1) / B;
    int e4 = e / 4;
    int ge4 = (e4 + B - 1) / B;
    int q = (n + 3) / 4;
    int gt = (4 * q + B - 1) / B;   // transform grid (4 threads' row-quads)

    // --- prologue ordered so launch #4 (the ncu sample) is the new transform ---
    k_hist_zero<<<gn, B>>>(n);                       // 1
    k_hist<<<ge4, B>>>(dst, e4);                     // 2
    k_scan_block<<<NBLK, SCAN_B>>>(n);               // 3 (also writes dinv)
    k_transform<128, 64><<<gt, B>>>(x, W1, n, q);    // 4  <- profiled
    k_scan_blk<<<1, 512>>>(NBLK);                    // 5
    k_scan_add<<<NBLK, SCAN_B>>>(n, e);              // 6
    k_place<<<ge4, B>>>(src, dst, e4);               // 7

    // layer 1 aggregate
    k_aggregate<64><<<(n * 16 + B - 1) / B, B>>>(b1, gh, n);

    // layer 2: 64 -> 64
    k_transform<64, 64><<<gt, B>>>(gh, W2, n, q);
    k_aggregate<64><<<(n * 16 + B - 1) / B, B>>>(b2, gh, n);

    // layer 3: 64 -> 64
    k_transform<64, 64><<<gt, B>>>(gh, W3, n, q);
    k_aggregate<64><<<(n * 16 + B - 1) / B, B>>>(b3, gh, n);

    // layer 4: 64 -> 32, aggregate fused with head
    k_transform<64, 32><<<gt, B>>>(gh, W4, n, q);
    k_aggregate_head<<<(n * 8 + B - 1) / B, B>>>(b4, Wh, bh, out, n);
}

// round 5
// speedup vs baseline: 2.2756x; 1.2271x over previous
#include <cuda_runtime.h>
#include <cuda_fp16.h>

// Problem constants (fixed by the dataset)
#define NN 100000
#define EE 1600000
#define SCAN_B 256
#define NBLK ((NN + SCAN_B - 1) / SCAN_B)   // 391

// Scratch (allocation-free rule: __device__ globals)
__device__ float  g_dinv[NN];
__device__ int    g_cnt[NN];
__device__ int    g_tmp[NN];
__device__ int    g_blk[512];
__device__ int    g_rowstart[NN + 1];
__device__ int    g_cursor[NN];
__device__ int    g_csrc[EE];
__device__ __half g_u[(size_t)NN * 64];     // fp16 messages
__device__ float  g_h[(size_t)NN * 64];

// ---------------------------------------------------------------------------
// packed f32x2 helpers (sm_103a)
// ---------------------------------------------------------------------------
__device__ __forceinline__ unsigned long long pack2(float a) {
    unsigned long long r;
    asm("mov.b64 %0, {%1, %1};" : "=l"(r) : "r"(__float_as_uint(a)));
    return r;
}
__device__ __forceinline__ void fma2(unsigned long long& d,
                                     unsigned long long a, unsigned long long b) {
    asm("fma.rn.f32x2 %0, %1, %2, %0;" : "+l"(d) : "l"(a), "l"(b));
}
__device__ __forceinline__ float2 unpk2(unsigned long long v) {
    float2 f;
    asm("mov.b64 {%0, %1}, %2;" : "=f"(f.x), "=f"(f.y) : "l"(v));
    return f;
}

// ---------------------------------------------------------------------------
// CSR build
// ---------------------------------------------------------------------------
__global__ void k_hist_zero(int n) {
    int i = blockIdx.x * blockDim.x + threadIdx.x;
    if (i < n) g_cnt[i] = 0;
}

__global__ void k_hist(const int* __restrict__ dst, int e4) {
    int i = blockIdx.x * blockDim.x + threadIdx.x;
    if (i < e4) {
        int4 d = ((const int4*)dst)[i];
        atomicAdd(&g_cnt[d.x], 1);
        atomicAdd(&g_cnt[d.y], 1);
        atomicAdd(&g_cnt[d.z], 1);
        atomicAdd(&g_cnt[d.w], 1);
    }
}

__global__ void k_scan_block(int n) {
    __shared__ int s[SCAN_B];
    int i = blockIdx.x * SCAN_B + threadIdx.x;
    int v = (i < n) ? g_cnt[i] : 0;
    if (i < n) g_dinv[i] = rsqrtf((float)(v + 1));  // +1 self-loop
    s[threadIdx.x] = v;
    __syncthreads();
    for (int o = 1; o < SCAN_B; o <<= 1) {
        int t = (threadIdx.x >= o) ? s[threadIdx.x - o] : 0;
        __syncthreads();
        s[threadIdx.x] += t;
        __syncthreads();
    }
    if (i < n) g_tmp[i] = s[threadIdx.x] - v;
    if (threadIdx.x == SCAN_B - 1) g_blk[blockIdx.x] = s[SCAN_B - 1];
}

__global__ void k_scan_blk(int nb) {
    __shared__ int s[512];
    int t = threadIdx.x;
    int v = (t < nb) ? g_blk[t] : 0;
    s[t] = v;
    __syncthreads();
    for (int o = 1; o < 512; o <<= 1) {
        int w = (t >= o) ? s[t - o] : 0;
        __syncthreads();
        s[t] += w;
        __syncthreads();
    }
    if (t < nb) g_blk[t] = s[t] - v;
}

__global__ void k_scan_add(int n, int e) {
    int i = blockIdx.x * SCAN_B + threadIdx.x;
    if (i < n) {
        int r = g_tmp[i] + g_blk[blockIdx.x];
        g_rowstart[i] = r;
        g_cursor[i] = r;
        if (i == n - 1) g_rowstart[n] = e;
    }
}

__global__ void k_place(const int* __restrict__ src, const int* __restrict__ dst, int e4) {
    int i = blockIdx.x * blockDim.x + threadIdx.x;
    if (i < e4) {
        int4 s = ((const int4*)src)[i];
        int4 d = ((const int4*)dst)[i];
        g_csrc[atomicAdd(&g_cursor[d.x], 1)] = s.x;
        g_csrc[atomicAdd(&g_cursor[d.y], 1)] = s.y;
        g_csrc[atomicAdd(&g_cursor[d.z], 1)] = s.z;
        g_csrc[atomicAdd(&g_cursor[d.w], 1)] = s.w;
    }
}

// ---------------------------------------------------------------------------
// Dense transform, smem-staged, bank-conflict-free:
//   u[row] = fp16( dinv[row] * (hin[row] @ W) )
// Block = 256 threads = 64 row-quads x 4 column groups. Each thread computes
// 4 rows (rq, rq+q, rq+2q, rq+3q) x COLS columns.
// X staged per 32-wide k-chunk, pitch 36 (%32==4 -> warp's 8 rows conflict-free).
// W staged once, pitch 88, cg bases {0,24,48,72} (mod-32 banks {0,24,16,8}
// -> every W LDS.128 is a 4-address conflict-free wavefront).
// ---------------------------------------------------------------------------
__device__ __forceinline__ int wbase(int cg) { return cg * 24; }

template <int IN, int OUT>
__global__ void __launch_bounds__(256, 2)
k_transform(const float* __restrict__ hin, const float* __restrict__ W, int n, int q) {
    constexpr int COLS = OUT / 4;      // 16 or 8
    constexpr int P = COLS / 2;        // u64 accumulators per row
    constexpr int PW = 88;
    constexpr int PX = 36;
    extern __shared__ float smem[];
    float* sW = smem;                  // IN * PW
    float* sX = smem + IN * PW;        // 256 * PX

    // stage W (swizzled layout)
    for (int i = threadIdx.x; i < IN * OUT; i += 256) {
        int k = i / OUT;
        int col = i - k * OUT;
        int cg = col / COLS;
        int cc = col - cg * COLS;
        sW[k * PW + wbase(cg) + cc] = W[i];
    }

    int tid = threadIdx.x;
    int rl = tid >> 2;                 // local row-quad 0..63
    int cg = tid & 3;
    int rq = blockIdx.x * 64 + rl;     // global row-quad
    int cb = wbase(cg);

    unsigned long long acc[4][P];
#pragma unroll
    for (int r = 0; r < 4; r++)
#pragma unroll
        for (int c = 0; c < P; c++) acc[r][c] = 0ull;

#pragma unroll
    for (int kc = 0; kc < IN / 32; kc++) {
        __syncthreads();               // also covers W staging on first pass
        // stage X chunk: 256 rows x 32 floats, coalesced
        for (int i = tid; i < 2048; i += 256) {
            int g = i >> 9;
            int rr = (i >> 3) & 63;
            int c4 = i & 7;
            int row = blockIdx.x * 64 + rr;
            row = (row < q) ? row + g * q : 0;
            if (row >= n) row = 0;
            *(float4*)&sX[(g * 64 + rr) * PX + c4 * 4] =
                *(const float4*)&hin[(size_t)row * IN + kc * 32 + c4 * 4];
        }
        __syncthreads();

#pragma unroll
        for (int k4 = 0; k4 < 8; k4++) {
            float4 x0 = *(const float4*)&sX[(0 * 64 + rl) * PX + k4 * 4];
            float4 x1 = *(const float4*)&sX[(1 * 64 + rl) * PX + k4 * 4];
            float4 x2 = *(const float4*)&sX[(2 * 64 + rl) * PX + k4 * 4];
            float4 x3 = *(const float4*)&sX[(3 * 64 + rl) * PX + k4 * 4];
            float xa0[4] = {x0.x, x0.y, x0.z, x0.w};
            float xa1[4] = {x1.x, x1.y, x1.z, x1.w};
            float xa2[4] = {x2.x, x2.y, x2.z, x2.w};
            float xa3[4] = {x3.x, x3.y, x3.z, x3.w};
#pragma unroll
            for (int kk = 0; kk < 4; kk++) {
                const ulonglong2* wr =
                    (const ulonglong2*)&sW[(kc * 32 + k4 * 4 + kk) * PW + cb];
                unsigned long long p0 = pack2(xa0[kk]);
                unsigned long long p1 = pack2(xa1[kk]);
                unsigned long long p2 = pack2(xa2[kk]);
                unsigned long long p3 = pack2(xa3[kk]);
#pragma unroll
                for (int c = 0; c < P / 2; c++) {
                    ulonglong2 w = wr[c];
                    fma2(acc[0][2 * c + 0], p0, w.x);
                    fma2(acc[0][2 * c + 1], p0, w.y);
                    fma2(acc[1][2 * c + 0], p1, w.x);
                    fma2(acc[1][2 * c + 1], p1, w.y);
                    fma2(acc[2][2 * c + 0], p2, w.x);
                    fma2(acc[2][2 * c + 1], p2, w.y);
                    fma2(acc[3][2 * c + 0], p3, w.x);
                    fma2(acc[3][2 * c + 1], p3, w.y);
                }
            }
        }
    }

    if (rq >= q) return;
#pragma unroll
    for (int r = 0; r < 4; r++) {
        int row = rq + r * q;
        if (row >= n) continue;
        float dv = g_dinv[row];
        unsigned int hh[P];
#pragma unroll
        for (int c = 0; c < P; c++) {
            float2 f = unpk2(acc[r][c]);
            __half2 h2 = __floats2half2_rn(f.x * dv, f.y * dv);
            hh[c] = *(unsigned int*)&h2;
        }
        unsigned int* dst = (unsigned int*)(g_u + (size_t)row * OUT + cg * COLS);
#pragma unroll
        for (int c = 0; c < P / 4; c++) {
            uint4 o = make_uint4(hh[4 * c + 0], hh[4 * c + 1], hh[4 * c + 2], hh[4 * c + 3]);
            ((uint4*)dst)[c] = o;
        }
    }
}

// ---------------------------------------------------------------------------
// fp16 gather helpers: lane covers 8 columns (one uint4 = 8 fp16)
// ---------------------------------------------------------------------------
__device__ __forceinline__ void acc8(float* a, uint4 v) {
    float2 f0 = __half22float2(*(__half2*)&v.x);
    float2 f1 = __half22float2(*(__half2*)&v.y);
    float2 f2 = __half22float2(*(__half2*)&v.z);
    float2 f3 = __half22float2(*(__half2*)&v.w);
    a[0] += f0.x; a[1] += f0.y; a[2] += f1.x; a[3] += f1.y;
    a[4] += f2.x; a[5] += f2.y; a[6] += f3.x; a[7] += f3.y;
}

// CSR gather-sum: 4-way unrolled, quad index prefetch, dual accumulator banks.
template <int L>   // L = OUT/8 lanes per node
__device__ __forceinline__ void gather_sum8(int node, int c8, float* a) {
    int s0 = g_rowstart[node];
    int s1 = g_rowstart[node + 1];
    const uint4* u4 = (const uint4*)g_u;

    float b[8];
#pragma unroll
    for (int i = 0; i < 8; i++) { a[i] = 0.f; b[i] = 0.f; }
    acc8(a, u4[(size_t)node * L + c8]);   // self-loop term

    int k = s0;
    int i0 = (k + 0 < s1) ? g_csrc[k + 0] : 0;
    int i1 = (k + 1 < s1) ? g_csrc[k + 1] : 0;
    int i2 = (k + 2 < s1) ? g_csrc[k + 2] : 0;
    int i3 = (k + 3 < s1) ? g_csrc[k + 3] : 0;
    while (k + 4 <= s1) {
        int j0 = i0, j1 = i1, j2 = i2, j3 = i3;
        i0 = (k + 4 < s1) ? g_csrc[k + 4] : 0;
        i1 = (k + 5 < s1) ? g_csrc[k + 5] : 0;
        i2 = (k + 6 < s1) ? g_csrc[k + 6] : 0;
        i3 = (k + 7 < s1) ? g_csrc[k + 7] : 0;
        uint4 v0 = u4[(size_t)j0 * L + c8];
        uint4 v1 = u4[(size_t)j1 * L + c8];
        uint4 v2 = u4[(size_t)j2 * L + c8];
        uint4 v3 = u4[(size_t)j3 * L + c8];
        acc8(a, v0); acc8(b, v1); acc8(a, v2); acc8(b, v3);
        k += 4;
    }
    if (k + 0 < s1) acc8(a, u4[(size_t)i0 * L + c8]);
    if (k + 1 < s1) acc8(b, u4[(size_t)i1 * L + c8]);
    if (k + 2 < s1) acc8(a, u4[(size_t)i2 * L + c8]);
#pragma unroll
    for (int i = 0; i < 8; i++) a[i] += b[i];
}

// ---------------------------------------------------------------------------
// Fused aggregate + finish: h[i] = relu(dinv[i]*(u[i]+sum u[j]) + b)  (fp32 out)
// ---------------------------------------------------------------------------
template <int OUT>
__global__ void k_aggregate(const float* __restrict__ b, float* __restrict__ hout, int n) {
    constexpr int L = OUT / 8;
    int t = blockIdx.x * blockDim.x + threadIdx.x;
    int node = t / L;
    int c8 = t - node * L;
    if (node >= n) return;

    float a[8];
    gather_sum8<L>(node, c8, a);

    float dv = g_dinv[node];
    float4 b0 = ((const float4*)b)[c8 * 2 + 0];
    float4 b1 = ((const float4*)b)[c8 * 2 + 1];
    float4 r0, r1;
    r0.x = fmaxf(fmaf(dv, a[0], b0.x), 0.f);
    r0.y = fmaxf(fmaf(dv, a[1], b0.y), 0.f);
    r0.z = fmaxf(fmaf(dv, a[2], b0.z), 0.f);
    r0.w = fmaxf(fmaf(dv, a[3], b0.w), 0.f);
    r1.x = fmaxf(fmaf(dv, a[4], b1.x), 0.f);
    r1.y = fmaxf(fmaf(dv, a[5], b1.y), 0.f);
    r1.z = fmaxf(fmaf(dv, a[6], b1.z), 0.f);
    r1.w = fmaxf(fmaf(dv, a[7], b1.w), 0.f);
    float4* dst = (float4*)(hout + (size_t)node * OUT + c8 * 8);
    dst[0] = r0;
    dst[1] = r1;
}

// ---------------------------------------------------------------------------
// Layer-4 aggregate fused with the output head (OUT=32, 4 lanes/node)
// ---------------------------------------------------------------------------
__global__ void k_aggregate_head(const float* __restrict__ b,
                                 const float* __restrict__ Wh,
                                 const float* __restrict__ bh,
                                 float* __restrict__ out, int n) {
    constexpr int L = 4;  // 32/8
    __shared__ float sW[96];
    __shared__ float sb[3];
    if (threadIdx.x < 96) sW[threadIdx.x] = Wh[threadIdx.x];
    if (threadIdx.x < 3) sb[threadIdx.x] = bh[threadIdx.x];
    __syncthreads();

    int t = blockIdx.x * blockDim.x + threadIdx.x;
    int node = t / L;
    int c8 = t - node * L;
    if (node >= n) return;

    float a[8];
    gather_sum8<L>(node, c8, a);

    float dv = g_dinv[node];
    float h[8];
#pragma unroll
    for (int i = 0; i < 8; i++)
        h[i] = fmaxf(fmaf(dv, a[i], b[c8 * 8 + i]), 0.f);

    float po[3];
#pragma unroll
    for (int j = 0; j < 3; j++) {
        float s = 0.f;
#pragma unroll
        for (int m = 0; m < 8; m++) s += h[m] * sW[(c8 * 8 + m) * 3 + j];
        po[j] = s;
    }
#pragma unroll
    for (int o = 2; o >= 1; o >>= 1) {
#pragma unroll
        for (int j = 0; j < 3; j++)
            po[j] += __shfl_down_sync(0xffffffffu, po[j], o, 4);
    }
    if (c8 == 0) {
        out[(size_t)node * 3 + 0] = po[0] + sb[0];
        out[(size_t)node * 3 + 1] = po[1] + sb[1];
        out[(size_t)node * 3 + 2] = po[2] + sb[2];
    }
}

// ---------------------------------------------------------------------------
extern "C" void kernel_launch(void* const* d_in, const int* in_sizes, int n_in,
                              void* d_out, int out_size) {
    const float* x  = (const float*)d_in[0];
    const int*   ei = (const int*)d_in[1];
    const float* W1 = (const float*)d_in[2];
    const float* b1 = (const float*)d_in[3];
    const float* W2 = (const float*)d_in[4];
    const float* b2 = (const float*)d_in[5];
    const float* W3 = (const float*)d_in[6];
    const float* b3 = (const float*)d_in[7];
    const float* W4 = (const float*)d_in[8];
    const float* b4 = (const float*)d_in[9];
    const float* Wh = (const float*)d_in[10];
    const float* bh = (const float*)d_in[11];
    float* out = (float*)d_out;

    int n = in_sizes[0] / 128;  // 100000
    int e = in_sizes[1] / 2;    // 1600000
    const int* src = ei;
    const int* dst = ei + e;

    void* gh_ptr = nullptr;
    cudaGetSymbolAddress(&gh_ptr, g_h);
    float* gh = (float*)gh_ptr;

    const int B = 256;
    int gn = (n + B - 1) / B;
    int e4 = e / 4;
    int ge4 = (e4 + B - 1) / B;
    int q = (n + 3) / 4;                 // 25000
    int gt = (q + 63) / 64;              // 391 transform blocks

    const int SM1 = (128 * 88 + 256 * 36) * 4;  // 81920 B
    const int SM2 = (64 * 88 + 256 * 36) * 4;   // 59392 B
    cudaFuncSetAttribute(k_transform<128, 64>, cudaFuncAttributeMaxDynamicSharedMemorySize, SM1);
    cudaFuncSetAttribute(k_transform<64, 64>,  cudaFuncAttributeMaxDynamicSharedMemorySize, SM2);
    cudaFuncSetAttribute(k_transform<64, 32>,  cudaFuncAttributeMaxDynamicSharedMemorySize, SM2);

    // --- prologue ordered so launch #4 (the ncu sample) is transform<128,64> ---
    k_hist_zero<<<gn, B>>>(n);                           // 1
    k_hist<<<ge4, B>>>(dst, e4);                         // 2
    k_scan_block<<<NBLK, SCAN_B>>>(n);                   // 3 (also writes dinv)
    k_transform<128, 64><<<gt, B, SM1>>>(x, W1, n, q);   // 4  <- profiled
    k_scan_blk<<<1, 512>>>(NBLK);                        // 5
    k_scan_add<<<NBLK, SCAN_B>>>(n, e);                  // 6
    k_place<<<ge4, B>>>(src, dst, e4);                   // 7

    // layer 1 aggregate
    k_aggregate<64><<<(n * 8 + B - 1) / B, B>>>(b1, gh, n);

    // layer 2: 64 -> 64
    k_transform<64, 64><<<gt, B, SM2>>>(gh, W2, n, q);
    k_aggregate<64><<<(n * 8 + B - 1) / B, B>>>(b2, gh, n);

    // layer 3: 64 -> 64
    k_transform<64, 64><<<gt, B, SM2>>>(gh, W3, n, q);
    k_aggregate<64><<<(n * 8 + B - 1) / B, B>>>(b3, gh, n);

    // layer 4: 64 -> 32, aggregate fused with head
    k_transform<64, 32><<<gt, B, SM2>>>(gh, W4, n, q);
    k_aggregate_head<<<(n * 4 + B - 1) / B, B>>>(b4, Wh, bh, out, n);
}

// round 7
// speedup vs baseline: 2.5909x; 1.1386x over previous
#include <cuda_runtime.h>
#include <cuda_fp16.h>
#include <mma.h>
#include <cstdint>

using namespace nvcuda;

// Problem constants (fixed by the dataset)
#define NN 100000
#define NPAD 100096                          // 782 * 128, wmma tail safety
#define EE 1600000
#define SCAN_B 256
#define NBLK ((NN + SCAN_B - 1) / SCAN_B)   // 391

// Scratch (allocation-free rule: __device__ globals)
__device__ float  g_dinv[NN];
__device__ int    g_cnt[NN];
__device__ int    g_tmp[NN];
__device__ int    g_blk[512];
__device__ int    g_rowstart[NN + 1];
__device__ int    g_cursor[NN];
__device__ int    g_csrc[EE];
__device__ __half g_u[(size_t)NPAD * 64];    // fp16 messages (padded rows stay 0)
__device__ __half g_h[(size_t)NPAD * 64];    // fp16 activations (padded rows stay 0)

// ---------------------------------------------------------------------------
// CSR build
// ---------------------------------------------------------------------------
__global__ void k_hist_zero(int n) {
    int i = blockIdx.x * blockDim.x + threadIdx.x;
    if (i < n) g_cnt[i] = 0;
}

__global__ void k_hist(const int* __restrict__ dst, int e4) {
    int i = blockIdx.x * blockDim.x + threadIdx.x;
    if (i < e4) {
        int4 d = ((const int4*)dst)[i];
        atomicAdd(&g_cnt[d.x], 1);
        atomicAdd(&g_cnt[d.y], 1);
        atomicAdd(&g_cnt[d.z], 1);
        atomicAdd(&g_cnt[d.w], 1);
    }
}

__global__ void k_scan_block(int n) {
    __shared__ int s[SCAN_B];
    int i = blockIdx.x * SCAN_B + threadIdx.x;
    int v = (i < n) ? g_cnt[i] : 0;
    if (i < n) g_dinv[i] = rsqrtf((float)(v + 1));  // +1 self-loop
    s[threadIdx.x] = v;
    __syncthreads();
    for (int o = 1; o < SCAN_B; o <<= 1) {
        int t = (threadIdx.x >= o) ? s[threadIdx.x - o] : 0;
        __syncthreads();
        s[threadIdx.x] += t;
        __syncthreads();
    }
    if (i < n) g_tmp[i] = s[threadIdx.x] - v;
    if (threadIdx.x == SCAN_B - 1) g_blk[blockIdx.x] = s[SCAN_B - 1];
}

__global__ void k_scan_blk(int nb) {
    __shared__ int s[512];
    int t = threadIdx.x;
    int v = (t < nb) ? g_blk[t] : 0;
    s[t] = v;
    __syncthreads();
    for (int o = 1; o < 512; o <<= 1) {
        int w = (t >= o) ? s[t - o] : 0;
        __syncthreads();
        s[t] += w;
        __syncthreads();
    }
    if (t < nb) g_blk[t] = s[t] - v;
}

__global__ void k_scan_add(int n, int e) {
    int i = blockIdx.x * SCAN_B + threadIdx.x;
    if (i < n) {
        int r = g_tmp[i] + g_blk[blockIdx.x];
        g_rowstart[i] = r;
        g_cursor[i] = r;
        if (i == n - 1) g_rowstart[n] = e;
    }
}

__global__ void k_place(const int* __restrict__ src, const int* __restrict__ dst, int e4) {
    int i = blockIdx.x * blockDim.x + threadIdx.x;
    if (i < e4) {
        int4 s = ((const int4*)src)[i];
        int4 d = ((const int4*)dst)[i];
        g_csrc[atomicAdd(&g_cursor[d.x], 1)] = s.x;
        g_csrc[atomicAdd(&g_cursor[d.y], 1)] = s.y;
        g_csrc[atomicAdd(&g_cursor[d.z], 1)] = s.z;
        g_csrc[atomicAdd(&g_cursor[d.w], 1)] = s.w;
    }
}

// ---------------------------------------------------------------------------
// WMMA transform:  u[row] = fp16( dinv[row] * (hin[row] @ W) )
// CTA = 128 rows x OUT cols, 8 warps x 16-row slabs, fp16 frags, fp32 accum.
//   FP32IN: A (fp32 x) converted to fp16 in smem.
//   else:   A loaded directly from global fp16 (g_h), L2-resident.
// W staged fp16 in smem (row-major [IN][OUT] = wmma B row-major directly).
// C via smem roundtrip for dinv scale + fp16 pack.
// ---------------------------------------------------------------------------
template <int IN, int OUT, bool FP32IN>
__global__ void __launch_bounds__(256)
k_wmma(const void* __restrict__ hin, const float* __restrict__ W, int n) {
    constexpr int LDA = IN + 8;
    constexpr int LDB = OUT + 8;
    constexpr int NT = OUT / 16;             // n-tiles per warp
    extern __shared__ char smraw[];
    __half* sB = (__half*)smraw;                          // IN * LDB
    float*  sC = (float*)(smraw + IN * LDB * 2);          // 128 * OUT
    __half* sA = (__half*)(sC + 128 * OUT);               // 128 * LDA (FP32IN only)

    int tid = threadIdx.x;
    int wid = tid >> 5;

    // stage B = fp16(W), row-major [IN][OUT]
    for (int i = tid; i < IN * OUT; i += 256) {
        int k = i / OUT, c = i - k * OUT;
        sB[k * LDB + c] = __float2half_rn(W[i]);
    }
    if (FP32IN) {
        // stage A: 128 rows x IN fp32 -> fp16
        for (int i = tid; i < 128 * IN / 4; i += 256) {
            int r = i / (IN / 4), c4 = i - r * (IN / 4);
            int row = blockIdx.x * 128 + r;
            int rr = (row < n) ? row : 0;
            float4 f = *(const float4*)((const float*)hin + (size_t)rr * IN + c4 * 4);
            __half2 h0 = __floats2half2_rn(f.x, f.y);
            __half2 h1 = __floats2half2_rn(f.z, f.w);
            *(uint32_t*)&sA[r * LDA + c4 * 4 + 0] = *(uint32_t*)&h0;
            *(uint32_t*)&sA[r * LDA + c4 * 4 + 2] = *(uint32_t*)&h1;
        }
    }
    __syncthreads();

    wmma::fragment<wmma::accumulator, 16, 16, 16, float> cf[NT];
#pragma unroll
    for (int j = 0; j < NT; j++) wmma::fill_fragment(cf[j], 0.f);

    const __half* gA = (const __half*)hin + (size_t)(blockIdx.x * 128 + wid * 16) * IN;

#pragma unroll
    for (int k = 0; k < IN / 16; k++) {
        wmma::fragment<wmma::matrix_a, 16, 16, 16, __half, wmma::row_major> af;
        if (FP32IN)
            wmma::load_matrix_sync(af, sA + wid * 16 * LDA + k * 16, LDA);
        else
            wmma::load_matrix_sync(af, gA + k * 16, IN);
#pragma unroll
        for (int j = 0; j < NT; j++) {
            wmma::fragment<wmma::matrix_b, 16, 16, 16, __half, wmma::row_major> bf;
            wmma::load_matrix_sync(bf, sB + k * 16 * LDB + j * 16, LDB);
            wmma::mma_sync(cf[j], af, bf, cf[j]);
        }
    }

#pragma unroll
    for (int j = 0; j < NT; j++)
        wmma::store_matrix_sync(sC + wid * 16 * OUT + j * 16, cf[j], OUT, wmma::mem_row_major);
    __syncthreads();

    // scale by dinv, pack fp16, write u
    constexpr int C8 = OUT / 8;
    for (int i = tid; i < 128 * C8; i += 256) {
        int r = i / C8, c8 = i - r * C8;
        int row = blockIdx.x * 128 + r;
        if (row >= n) continue;
        float dv = g_dinv[row];
        const float* p = sC + r * OUT + c8 * 8;
        uint32_t q[4];
#pragma unroll
        for (int j = 0; j < 4; j++) {
            __half2 h = __floats2half2_rn(p[2 * j] * dv, p[2 * j + 1] * dv);
            q[j] = *(uint32_t*)&h;
        }
        ((uint4*)(g_u + (size_t)row * OUT))[c8] = make_uint4(q[0], q[1], q[2], q[3]);
    }
}

// ---------------------------------------------------------------------------
// fp16 gather helpers: lane covers 8 columns (one uint4 = 8 fp16)
// ---------------------------------------------------------------------------
__device__ __forceinline__ void acc8(float* a, uint4 v) {
    float2 f0 = __half22float2(*(__half2*)&v.x);
    float2 f1 = __half22float2(*(__half2*)&v.y);
    float2 f2 = __half22float2(*(__half2*)&v.z);
    float2 f3 = __half22float2(*(__half2*)&v.w);
    a[0] += f0.x; a[1] += f0.y; a[2] += f1.x; a[3] += f1.y;
    a[4] += f2.x; a[5] += f2.y; a[6] += f3.x; a[7] += f3.y;
}

template <int L>   // L = OUT/8 lanes per node
__device__ __forceinline__ void gather_sum8(int node, int c8, float* a) {
    int s0 = g_rowstart[node];
    int s1 = g_rowstart[node + 1];
    const uint4* u4 = (const uint4*)g_u;

    float b[8];
#pragma unroll
    for (int i = 0; i < 8; i++) { a[i] = 0.f; b[i] = 0.f; }
    acc8(a, u4[(size_t)node * L + c8]);   // self-loop term

    int k = s0;
    int i0 = (k + 0 < s1) ? g_csrc[k + 0] : 0;
    int i1 = (k + 1 < s1) ? g_csrc[k + 1] : 0;
    int i2 = (k + 2 < s1) ? g_csrc[k + 2] : 0;
    int i3 = (k + 3 < s1) ? g_csrc[k + 3] : 0;
    while (k + 4 <= s1) {
        int j0 = i0, j1 = i1, j2 = i2, j3 = i3;
        i0 = (k + 4 < s1) ? g_csrc[k + 4] : 0;
        i1 = (k + 5 < s1) ? g_csrc[k + 5] : 0;
        i2 = (k + 6 < s1) ? g_csrc[k + 6] : 0;
        i3 = (k + 7 < s1) ? g_csrc[k + 7] : 0;
        uint4 v0 = u4[(size_t)j0 * L + c8];
        uint4 v1 = u4[(size_t)j1 * L + c8];
        uint4 v2 = u4[(size_t)j2 * L + c8];
        uint4 v3 = u4[(size_t)j3 * L + c8];
        acc8(a, v0); acc8(b, v1); acc8(a, v2); acc8(b, v3);
        k += 4;
    }
    if (k + 0 < s1) acc8(a, u4[(size_t)i0 * L + c8]);
    if (k + 1 < s1) acc8(b, u4[(size_t)i1 * L + c8]);
    if (k + 2 < s1) acc8(a, u4[(size_t)i2 * L + c8]);
#pragma unroll
    for (int i = 0; i < 8; i++) a[i] += b[i];
}

// ---------------------------------------------------------------------------
// Fused aggregate + finish: h = relu(dinv*(u_self + sum u_j) + b), fp16 out
// ---------------------------------------------------------------------------
template <int OUT>
__global__ void k_aggregate(const float* __restrict__ b, int n) {
    constexpr int L = OUT / 8;
    int t = blockIdx.x * blockDim.x + threadIdx.x;
    int node = t / L;
    int c8 = t - node * L;
    if (node >= n) return;

    float a[8];
    gather_sum8<L>(node, c8, a);

    float dv = g_dinv[node];
    const float* bb = b + c8 * 8;
    uint32_t p[4];
#pragma unroll
    for (int j = 0; j < 4; j++) {
        float r0 = fmaxf(fmaf(dv, a[2 * j + 0], bb[2 * j + 0]), 0.f);
        float r1 = fmaxf(fmaf(dv, a[2 * j + 1], bb[2 * j + 1]), 0.f);
        __half2 h = __floats2half2_rn(r0, r1);
        p[j] = *(uint32_t*)&h;
    }
    ((uint4*)(g_h + (size_t)node * OUT + c8 * 8))[0] = make_uint4(p[0], p[1], p[2], p[3]);
}

// ---------------------------------------------------------------------------
// Layer-4 aggregate fused with the output head (OUT=32, 4 lanes/node)
// ---------------------------------------------------------------------------
__global__ void k_aggregate_head(const float* __restrict__ b,
                                 const float* __restrict__ Wh,
                                 const float* __restrict__ bh,
                                 float* __restrict__ out, int n) {
    constexpr int L = 4;  // 32/8
    __shared__ float sW[96];
    __shared__ float sb[3];
    if (threadIdx.x < 96) sW[threadIdx.x] = Wh[threadIdx.x];
    if (threadIdx.x < 3) sb[threadIdx.x] = bh[threadIdx.x];
    __syncthreads();

    int t = blockIdx.x * blockDim.x + threadIdx.x;
    int node = t / L;
    int c8 = t - node * L;
    if (node >= n) return;

    float a[8];
    gather_sum8<L>(node, c8, a);

    float dv = g_dinv[node];
    float h[8];
#pragma unroll
    for (int i = 0; i < 8; i++)
        h[i] = fmaxf(fmaf(dv, a[i], b[c8 * 8 + i]), 0.f);

    float po[3];
#pragma unroll
    for (int j = 0; j < 3; j++) {
        float s = 0.f;
#pragma unroll
        for (int m = 0; m < 8; m++) s += h[m] * sW[(c8 * 8 + m) * 3 + j];
        po[j] = s;
    }
#pragma unroll
    for (int o = 2; o >= 1; o >>= 1) {
#pragma unroll
        for (int j = 0; j < 3; j++)
            po[j] += __shfl_down_sync(0xffffffffu, po[j], o, 4);
    }
    if (c8 == 0) {
        out[(size_t)node * 3 + 0] = po[0] + sb[0];
        out[(size_t)node * 3 + 1] = po[1] + sb[1];
        out[(size_t)node * 3 + 2] = po[2] + sb[2];
    }
}

// ---------------------------------------------------------------------------
extern "C" void kernel_launch(void* const* d_in, const int* in_sizes, int n_in,
                              void* d_out, int out_size) {
    const float* x  = (const float*)d_in[0];
    const int*   ei = (const int*)d_in[1];
    const float* W1 = (const float*)d_in[2];
    const float* b1 = (const float*)d_in[3];
    const float* W2 = (const float*)d_in[4];
    const float* b2 = (const float*)d_in[5];
    const float* W3 = (const float*)d_in[6];
    const float* b3 = (const float*)d_in[7];
    const float* W4 = (const float*)d_in[8];
    const float* b4 = (const float*)d_in[9];
    const float* Wh = (const float*)d_in[10];
    const float* bh = (const float*)d_in[11];
    float* out = (float*)d_out;

    int n = in_sizes[0] / 128;  // 100000
    int e = in_sizes[1] / 2;    // 1600000
    const int* src = ei;
    const int* dst = ei + e;

    void* gh_ptr = nullptr;
    cudaGetSymbolAddress(&gh_ptr, g_h);
    const void* gh = gh_ptr;

    const int B = 256;
    int gn = (n + B - 1) / B;
    int e4 = e / 4;
    int ge4 = (e4 + B - 1) / B;
    int gm = (n + 127) / 128;   // 782 M-tiles

    // smem: B (IN*(OUT+8)*2) + C (128*OUT*4) + A (FP32IN: 128*(IN+8)*2)
    const int SM1 = 128 * 72 * 2 + 128 * 64 * 4 + 128 * 136 * 2;  // 86016
    const int SM2 = 64 * 72 * 2 + 128 * 64 * 4;                   // 41984
    const int SM4 = 64 * 40 * 2 + 128 * 32 * 4;                   // 21504
    cudaFuncSetAttribute(k_wmma<128, 64, true>,  cudaFuncAttributeMaxDynamicSharedMemorySize, SM1);
    cudaFuncSetAttribute(k_wmma<64, 64, false>,  cudaFuncAttributeMaxDynamicSharedMemorySize, SM2);
    cudaFuncSetAttribute(k_wmma<64, 32, false>,  cudaFuncAttributeMaxDynamicSharedMemorySize, SM4);

    // --- prologue ordered so launch #4 (the ncu sample) is the wmma transform ---
    k_hist_zero<<<gn, B>>>(n);                                   // 1
    k_hist<<<ge4, B>>>(dst, e4);                                 // 2
    k_scan_block<<<NBLK, SCAN_B>>>(n);                           // 3 (also dinv)
    k_wmma<128, 64, true><<<gm, 256, SM1>>>(x, W1, n);           // 4  <- profiled
    k_scan_blk<<<1, 512>>>(NBLK);                                // 5
    k_scan_add<<<NBLK, SCAN_B>>>(n, e);                          // 6
    k_place<<<ge4, B>>>(src, dst, e4);                           // 7

    // layer 1 aggregate
    k_aggregate<64><<<(n * 8 + B - 1) / B, B>>>(b1, n);

    // layer 2: 64 -> 64
    k_wmma<64, 64, false><<<gm, 256, SM2>>>(gh, W2, n);
    k_aggregate<64><<<(n * 8 + B - 1) / B, B>>>(b2, n);

    // layer 3: 64 -> 64
    k_wmma<64, 64, false><<<gm, 256, SM2>>>(gh, W3, n);
    k_aggregate<64><<<(n * 8 + B - 1) / B, B>>>(b3, n);

    // layer 4: 64 -> 32, aggregate fused with head
    k_wmma<64, 32, false><<<gm, 256, SM4>>>(gh, W4, n);
    k_aggregate_head<<<(n * 4 + B - 1) / B, B>>>(b4, Wh, bh, out, n);
}